// round 16
// baseline (speedup 1.0000x reference)
#include <cuda_runtime.h>
#include <cuda_bf16.h>
#include <cstdint>

#define N_NODES 50000
#define N_EDGES 800000
#define IN_DIM  256
#define OUT_DIM 64
#define CAP     96          // bucket capacity per node (Poisson(16): P(>96) ~ 0)

#define NBLK    296         // 2 blocks/SM x 148 SMs (GB300 has >=148) — all co-resident

// ---- device-global scratch (allocation-free rule) ----
__device__ float          g_support[(size_t)N_NODES * OUT_DIM];  // 12.8 MB
__device__ __nv_bfloat16  g_WT_hi[OUT_DIM * IN_DIM];             // W^T hi (bf16)
__device__ __nv_bfloat16  g_WT_lo[OUT_DIM * IN_DIM];             // W^T lo (bf16)
__device__ int            g_count[N_NODES];                      // per-dst degree
__device__ int2           g_bucket[(size_t)N_NODES * CAP];       // 38.4 MB
__device__ unsigned       g_bar_ctr;                             // cumulative barrier tickets
__device__ int            g_chunk;                               // edge-chunk steal counter

// mma.sync m16n8k16 bf16 (sm_80+ plain feature — OK at .target sm_103)
__device__ __forceinline__ void mma_bf16(float* d, uint32_t a0, uint32_t a1,
                                         uint32_t a2, uint32_t a3,
                                         uint32_t b0, uint32_t b1) {
    asm volatile(
        "mma.sync.aligned.m16n8k16.row.col.f32.bf16.bf16.f32 "
        "{%0,%1,%2,%3}, {%4,%5,%6,%7}, {%8,%9}, {%0,%1,%2,%3};"
        : "+f"(d[0]), "+f"(d[1]), "+f"(d[2]), "+f"(d[3])
        : "r"(a0), "r"(a1), "r"(a2), "r"(a3), "r"(b0), "r"(b1));
}

// Software grid barrier: cumulative ticket counter, no reset ever needed.
// Rounds are globally ordered, so each round's NBLK tickets are contiguous.
__device__ __forceinline__ void grid_sync() {
    __syncthreads();
    __threadfence();
    if (threadIdx.x == 0) {
        unsigned t = atomicAdd(&g_bar_ctr, 1u);
        unsigned target = t - (t % NBLK) + NBLK;
        while (*(volatile unsigned*)&g_bar_ctr < target) { }
    }
    __syncthreads();
    __threadfence();
}

// ---------------------------------------------------------------------------
// GEMM tile body (R14-proven): 128-row tile, bf16 3-term hi/lo, 8 warps.
// ---------------------------------------------------------------------------
#define TILE_M 128
#define KC     32
#define NCHUNK (IN_DIM / KC)    // 8
#define APAD   34               // bf16 per row (stride 17 words)
#define GEMM_TILES ((N_NODES + TILE_M - 1) / TILE_M)   // 391
#define EDGE_CHUNKS (N_EDGES / 256)                    // 3125 (exact)
#define SPMM_ITERS (N_NODES / 16)                      // 3125 (exact)

__device__ __forceinline__ void gemm_body(const float* __restrict__ X, int blk) {
    __shared__ __nv_bfloat16 sAhi[TILE_M][APAD];
    __shared__ __nv_bfloat16 sAlo[TILE_M][APAD];
    __shared__ __nv_bfloat16 sBhi[OUT_DIM][APAD];
    __shared__ __nv_bfloat16 sBlo[OUT_DIM][APAD];

    const int tid  = threadIdx.x;
    const int wid  = tid >> 5;
    const int lane = tid & 31;
    const int gid  = lane >> 2;     // 0..7
    const int tig  = lane & 3;      // 0..3
    const int row0 = blk * TILE_M;

    float acc[8][4];
#pragma unroll
    for (int nt = 0; nt < 8; nt++)
#pragma unroll
        for (int q = 0; q < 4; q++) acc[nt][q] = 0.f;

    for (int ch = 0; ch < NCHUNK; ch++) {
        const int kc = ch * KC;
#pragma unroll
        for (int i = tid; i < TILE_M * (KC / 4); i += 256) {   // 1024 float4
            const int r = i >> 3;
            const int q = i & 7;
            const int grow = row0 + r;
            float4 x = make_float4(0.f, 0.f, 0.f, 0.f);
            if (grow < N_NODES)
                x = *reinterpret_cast<const float4*>(X + (size_t)grow * IN_DIM + kc + q * 4);
            __nv_bfloat162 h0 = make_bfloat162(__float2bfloat16_rn(x.x), __float2bfloat16_rn(x.y));
            __nv_bfloat162 h1 = make_bfloat162(__float2bfloat16_rn(x.z), __float2bfloat16_rn(x.w));
            __nv_bfloat162 l0 = make_bfloat162(
                __float2bfloat16_rn(x.x - __bfloat162float(h0.x)),
                __float2bfloat16_rn(x.y - __bfloat162float(h0.y)));
            __nv_bfloat162 l1 = make_bfloat162(
                __float2bfloat16_rn(x.z - __bfloat162float(h1.x)),
                __float2bfloat16_rn(x.w - __bfloat162float(h1.y)));
            *reinterpret_cast<__nv_bfloat162*>(&sAhi[r][q * 4])     = h0;
            *reinterpret_cast<__nv_bfloat162*>(&sAhi[r][q * 4 + 2]) = h1;
            *reinterpret_cast<__nv_bfloat162*>(&sAlo[r][q * 4])     = l0;
            *reinterpret_cast<__nv_bfloat162*>(&sAlo[r][q * 4 + 2]) = l1;
        }
#pragma unroll
        for (int i = tid; i < OUT_DIM * (KC / 2); i += 256) {  // 1024 words
            const int n  = i >> 4;
            const int wk = i & 15;
            uint32_t whi = *reinterpret_cast<const uint32_t*>(g_WT_hi + (size_t)n * IN_DIM + kc + wk * 2);
            uint32_t wlo = *reinterpret_cast<const uint32_t*>(g_WT_lo + (size_t)n * IN_DIM + kc + wk * 2);
            *reinterpret_cast<uint32_t*>(&sBhi[n][wk * 2]) = whi;
            *reinterpret_cast<uint32_t*>(&sBlo[n][wk * 2]) = wlo;
        }
        __syncthreads();

        const int ar = wid * 16 + gid;
#pragma unroll
        for (int ks = 0; ks < KC / 16; ks++) {
            const int k0w = ks * 8;
            uint32_t ahi0 = *reinterpret_cast<const uint32_t*>(&sAhi[ar][(k0w + tig) * 2]);
            uint32_t ahi1 = *reinterpret_cast<const uint32_t*>(&sAhi[ar + 8][(k0w + tig) * 2]);
            uint32_t ahi2 = *reinterpret_cast<const uint32_t*>(&sAhi[ar][(k0w + 4 + tig) * 2]);
            uint32_t ahi3 = *reinterpret_cast<const uint32_t*>(&sAhi[ar + 8][(k0w + 4 + tig) * 2]);
            uint32_t alo0 = *reinterpret_cast<const uint32_t*>(&sAlo[ar][(k0w + tig) * 2]);
            uint32_t alo1 = *reinterpret_cast<const uint32_t*>(&sAlo[ar + 8][(k0w + tig) * 2]);
            uint32_t alo2 = *reinterpret_cast<const uint32_t*>(&sAlo[ar][(k0w + 4 + tig) * 2]);
            uint32_t alo3 = *reinterpret_cast<const uint32_t*>(&sAlo[ar + 8][(k0w + 4 + tig) * 2]);
#pragma unroll
            for (int nt = 0; nt < 8; nt++) {
                const int br = nt * 8 + gid;
                uint32_t bh0 = *reinterpret_cast<const uint32_t*>(&sBhi[br][(k0w + tig) * 2]);
                uint32_t bh1 = *reinterpret_cast<const uint32_t*>(&sBhi[br][(k0w + 4 + tig) * 2]);
                uint32_t bl0 = *reinterpret_cast<const uint32_t*>(&sBlo[br][(k0w + tig) * 2]);
                uint32_t bl1 = *reinterpret_cast<const uint32_t*>(&sBlo[br][(k0w + 4 + tig) * 2]);
                mma_bf16(acc[nt], ahi0, ahi1, ahi2, ahi3, bh0, bh1);   // hi*hi
                mma_bf16(acc[nt], alo0, alo1, alo2, alo3, bh0, bh1);   // lo*hi
                mma_bf16(acc[nt], ahi0, ahi1, ahi2, ahi3, bl0, bl1);   // hi*lo
            }
        }
        __syncthreads();
    }

    const int r0 = row0 + wid * 16 + gid;
#pragma unroll
    for (int nt = 0; nt < 8; nt++) {
        const int col = nt * 8 + tig * 2;
        if (r0 < N_NODES)
            *reinterpret_cast<float2*>(g_support + (size_t)r0 * OUT_DIM + col) =
                make_float2(acc[nt][0], acc[nt][1]);
        if (r0 + 8 < N_NODES)
            *reinterpret_cast<float2*>(g_support + (size_t)(r0 + 8) * OUT_DIM + col) =
                make_float2(acc[nt][2], acc[nt][3]);
    }
}

// ---------------------------------------------------------------------------
// Persistent mono-kernel: prep -> barrier -> gemm+build -> barrier -> spmm.
// Exactly NBLK co-resident blocks (launch_bounds(256,2) + 26KB static smem).
// ---------------------------------------------------------------------------
__global__ __launch_bounds__(256, 2) void mono_kernel(const float* __restrict__ X,
                                                      const float* __restrict__ W,
                                                      const float* __restrict__ bias,
                                                      const float* __restrict__ edge_val,
                                                      const int* __restrict__ edge_src,
                                                      const int* __restrict__ edge_dst,
                                                      float* __restrict__ out) {
    const int blk = blockIdx.x;
    const int tid = threadIdx.x;
    const int gtid = blk * 256 + tid;

    // ---- Phase 0: prep (zero counts, split W^T, reset steal counter) ----
    {
        const int4 z = make_int4(0, 0, 0, 0);
        for (int i = gtid; i < N_NODES / 4; i += NBLK * 256)
            reinterpret_cast<int4*>(g_count)[i] = z;
        for (int idx = gtid; idx < OUT_DIM * IN_DIM; idx += NBLK * 256) {
            int n = idx >> 8;
            int k = idx & 255;
            float x = W[k * OUT_DIM + n];
            __nv_bfloat16 hi = __float2bfloat16_rn(x);
            g_WT_hi[idx] = hi;
            g_WT_lo[idx] = __float2bfloat16_rn(x - __bfloat162float(hi));
        }
        if (gtid == 0) g_chunk = 0;
    }
    grid_sync();

    // ---- Phase 1: gemm tiles (static) + edge build (dynamic stealing) ----
    for (int t = blk; t < GEMM_TILES; t += NBLK)
        gemm_body(X, t);

    {
        __shared__ int sc;
        for (;;) {
            if (tid == 0) sc = atomicAdd(&g_chunk, 1);
            __syncthreads();
            const int c = sc;
            __syncthreads();
            if (c >= EDGE_CHUNKS) break;
            const int i = c * 256 + tid;       // always < N_EDGES (exact chunks)
            int d = __ldg(&edge_dst[i]);
            int s = __ldg(&edge_src[i]);
            float v = __ldg(&edge_val[i]);
            int pos = atomicAdd(&g_count[d], 1);
            if (pos < CAP)
                g_bucket[(unsigned)d * CAP + (unsigned)pos] = make_int2(s, __float_as_int(v));
        }
    }
    grid_sync();

    // ---- Phase 2: segmented SpMM (half-warp per node, R14-proven body) ----
    {
        const int sub = tid >> 4;              // 0..15 (node slot in block)
        const int l   = tid & 15;              // float4 lane
        const float4 bseed = reinterpret_cast<const float4*>(bias)[l];
        const float4* sup = reinterpret_cast<const float4*>(g_support);

        for (int it = blk; it < SPMM_ITERS; it += NBLK) {
            const int g = it * 16 + sub;       // node id, always < N_NODES
            int cnt = g_count[g];
            if (cnt > CAP) cnt = CAP;
            const int2* bkt = g_bucket + (unsigned)g * CAP;

            float4 acc = bseed;
            int e = 0;
            for (; e + 1 < cnt; e += 2) {
                int2 p0 = bkt[e];
                int2 p1 = bkt[e + 1];
                float4 s0 = sup[(unsigned)p0.x * 16u + l];
                float4 s1 = sup[(unsigned)p1.x * 16u + l];
                float v0 = __int_as_float(p0.y);
                float v1 = __int_as_float(p1.y);
                acc.x = fmaf(v0, s0.x, acc.x); acc.y = fmaf(v0, s0.y, acc.y);
                acc.z = fmaf(v0, s0.z, acc.z); acc.w = fmaf(v0, s0.w, acc.w);
                acc.x = fmaf(v1, s1.x, acc.x); acc.y = fmaf(v1, s1.y, acc.y);
                acc.z = fmaf(v1, s1.z, acc.z); acc.w = fmaf(v1, s1.w, acc.w);
            }
            if (e < cnt) {
                int2 p = bkt[e];
                float4 s = sup[(unsigned)p.x * 16u + l];
                float v = __int_as_float(p.y);
                acc.x = fmaf(v, s.x, acc.x);
                acc.y = fmaf(v, s.y, acc.y);
                acc.z = fmaf(v, s.z, acc.z);
                acc.w = fmaf(v, s.w, acc.w);
            }
            reinterpret_cast<float4*>(out)[(unsigned)g * 16u + l] = acc;
        }
    }
}

// ---------------------------------------------------------------------------
extern "C" void kernel_launch(void* const* d_in, const int* in_sizes, int n_in,
                              void* d_out, int out_size) {
    const float* X    = (const float*)d_in[0];     // [50000, 256]
    const float* W    = (const float*)d_in[1];     // [256, 64]
    const float* bias = (const float*)d_in[2];     // [64]
    const float* ev   = (const float*)d_in[3];     // [800000]
    const int*   es   = (const int*)d_in[4];       // [800000] int32
    const int*   ed   = (const int*)d_in[5];       // [800000] int32
    float* out = (float*)d_out;                    // [50000, 64]

    mono_kernel<<<NBLK, 256>>>(X, W, bias, ev, es, ed, out);
}

// round 17
// speedup vs baseline: 1.7968x; 1.7968x over previous
#include <cuda_runtime.h>
#include <cuda_bf16.h>
#include <cuda_fp16.h>
#include <cstdint>

#define N_NODES 50000
#define N_EDGES 800000
#define IN_DIM  256
#define OUT_DIM 64
#define CAP     96          // bucket capacity per node (Poisson(16) tail: P(>96) ~ 0)

// ---- device-global scratch (allocation-free rule) ----
__device__ __half         g_support[(size_t)N_NODES * OUT_DIM];  // 6.4 MB (fp16!)
__device__ __nv_bfloat16  g_WT_hi[OUT_DIM * IN_DIM];             // W^T hi (bf16)
__device__ __nv_bfloat16  g_WT_lo[OUT_DIM * IN_DIM];             // W^T lo (bf16)
__device__ int            g_count[N_NODES];                      // per-dst degree
__device__ int2           g_bucket[(size_t)N_NODES * CAP];       // 38.4 MB

// mma.sync m16n8k16 bf16 (sm_80+ plain feature — OK at .target sm_103)
__device__ __forceinline__ void mma_bf16(float* d, uint32_t a0, uint32_t a1,
                                         uint32_t a2, uint32_t a3,
                                         uint32_t b0, uint32_t b1) {
    asm volatile(
        "mma.sync.aligned.m16n8k16.row.col.f32.bf16.bf16.f32 "
        "{%0,%1,%2,%3}, {%4,%5,%6,%7}, {%8,%9}, {%0,%1,%2,%3};"
        : "+f"(d[0]), "+f"(d[1]), "+f"(d[2]), "+f"(d[3])
        : "r"(a0), "r"(a1), "r"(a2), "r"(a3), "r"(b0), "r"(b1));
}

// ---------------------------------------------------------------------------
// Prep: zero g_count + split W [K,N] -> W^T [N,K] into bf16 hi/lo.
// ---------------------------------------------------------------------------
__global__ __launch_bounds__(256) void prep_kernel(const float* __restrict__ W) {
    int idx = blockIdx.x * 256 + threadIdx.x;
    if (idx < N_NODES) g_count[idx] = 0;
    if (idx < OUT_DIM * IN_DIM) {
        int n = idx >> 8;            // 0..63
        int k = idx & 255;           // 0..255
        float x = W[k * OUT_DIM + n];
        __nv_bfloat16 hi = __float2bfloat16_rn(x);
        g_WT_hi[idx] = hi;
        g_WT_lo[idx] = __float2bfloat16_rn(x - __bfloat162float(hi));
    }
}

// ---------------------------------------------------------------------------
// FUSED kernel: blocks [0, GEMM_BLOCKS) run the bf16 tensor GEMM tile;
// blocks [GEMM_BLOCKS, ...) run the bucket build (1 edge / thread).
// ---------------------------------------------------------------------------
#define TILE_M 128
#define KC     32
#define NCHUNK (IN_DIM / KC)    // 8
#define APAD   34               // bf16 per row (stride 17 words)
#define GEMM_BLOCKS ((N_NODES + TILE_M - 1) / TILE_M)          // 391
#define BUILD_BLOCKS ((N_EDGES + 255) / 256)                   // 3125
#define FUSED_BLOCKS (GEMM_BLOCKS + BUILD_BLOCKS)              // 3516

__device__ __forceinline__ void gemm_body(const float* __restrict__ X, int blk) {
    __shared__ __nv_bfloat16 sAhi[TILE_M][APAD];
    __shared__ __nv_bfloat16 sAlo[TILE_M][APAD];
    __shared__ __nv_bfloat16 sBhi[OUT_DIM][APAD];
    __shared__ __nv_bfloat16 sBlo[OUT_DIM][APAD];

    const int tid  = threadIdx.x;
    const int wid  = tid >> 5;
    const int lane = tid & 31;
    const int gid  = lane >> 2;     // 0..7
    const int tig  = lane & 3;      // 0..3
    const int row0 = blk * TILE_M;

    float acc[8][4];
#pragma unroll
    for (int nt = 0; nt < 8; nt++)
#pragma unroll
        for (int q = 0; q < 4; q++) acc[nt][q] = 0.f;

    for (int ch = 0; ch < NCHUNK; ch++) {
        const int kc = ch * KC;
#pragma unroll
        for (int i = tid; i < TILE_M * (KC / 4); i += 256) {   // 1024 float4
            const int r = i >> 3;
            const int q = i & 7;
            const int grow = row0 + r;
            float4 x = make_float4(0.f, 0.f, 0.f, 0.f);
            if (grow < N_NODES)
                x = *reinterpret_cast<const float4*>(X + (size_t)grow * IN_DIM + kc + q * 4);
            __nv_bfloat162 h0 = make_bfloat162(__float2bfloat16_rn(x.x), __float2bfloat16_rn(x.y));
            __nv_bfloat162 h1 = make_bfloat162(__float2bfloat16_rn(x.z), __float2bfloat16_rn(x.w));
            __nv_bfloat162 l0 = make_bfloat162(
                __float2bfloat16_rn(x.x - __bfloat162float(h0.x)),
                __float2bfloat16_rn(x.y - __bfloat162float(h0.y)));
            __nv_bfloat162 l1 = make_bfloat162(
                __float2bfloat16_rn(x.z - __bfloat162float(h1.x)),
                __float2bfloat16_rn(x.w - __bfloat162float(h1.y)));
            *reinterpret_cast<__nv_bfloat162*>(&sAhi[r][q * 4])     = h0;
            *reinterpret_cast<__nv_bfloat162*>(&sAhi[r][q * 4 + 2]) = h1;
            *reinterpret_cast<__nv_bfloat162*>(&sAlo[r][q * 4])     = l0;
            *reinterpret_cast<__nv_bfloat162*>(&sAlo[r][q * 4 + 2]) = l1;
        }
#pragma unroll
        for (int i = tid; i < OUT_DIM * (KC / 2); i += 256) {  // 1024 words
            const int n  = i >> 4;
            const int wk = i & 15;
            uint32_t whi = *reinterpret_cast<const uint32_t*>(g_WT_hi + (size_t)n * IN_DIM + kc + wk * 2);
            uint32_t wlo = *reinterpret_cast<const uint32_t*>(g_WT_lo + (size_t)n * IN_DIM + kc + wk * 2);
            *reinterpret_cast<uint32_t*>(&sBhi[n][wk * 2]) = whi;
            *reinterpret_cast<uint32_t*>(&sBlo[n][wk * 2]) = wlo;
        }
        __syncthreads();

        const int ar = wid * 16 + gid;
#pragma unroll
        for (int ks = 0; ks < KC / 16; ks++) {
            const int k0w = ks * 8;
            uint32_t ahi0 = *reinterpret_cast<const uint32_t*>(&sAhi[ar][(k0w + tig) * 2]);
            uint32_t ahi1 = *reinterpret_cast<const uint32_t*>(&sAhi[ar + 8][(k0w + tig) * 2]);
            uint32_t ahi2 = *reinterpret_cast<const uint32_t*>(&sAhi[ar][(k0w + 4 + tig) * 2]);
            uint32_t ahi3 = *reinterpret_cast<const uint32_t*>(&sAhi[ar + 8][(k0w + 4 + tig) * 2]);
            uint32_t alo0 = *reinterpret_cast<const uint32_t*>(&sAlo[ar][(k0w + tig) * 2]);
            uint32_t alo1 = *reinterpret_cast<const uint32_t*>(&sAlo[ar + 8][(k0w + tig) * 2]);
            uint32_t alo2 = *reinterpret_cast<const uint32_t*>(&sAlo[ar][(k0w + 4 + tig) * 2]);
            uint32_t alo3 = *reinterpret_cast<const uint32_t*>(&sAlo[ar + 8][(k0w + 4 + tig) * 2]);
#pragma unroll
            for (int nt = 0; nt < 8; nt++) {
                const int br = nt * 8 + gid;
                uint32_t bh0 = *reinterpret_cast<const uint32_t*>(&sBhi[br][(k0w + tig) * 2]);
                uint32_t bh1 = *reinterpret_cast<const uint32_t*>(&sBhi[br][(k0w + 4 + tig) * 2]);
                uint32_t bl0 = *reinterpret_cast<const uint32_t*>(&sBlo[br][(k0w + tig) * 2]);
                uint32_t bl1 = *reinterpret_cast<const uint32_t*>(&sBlo[br][(k0w + 4 + tig) * 2]);
                mma_bf16(acc[nt], ahi0, ahi1, ahi2, ahi3, bh0, bh1);   // hi*hi
                mma_bf16(acc[nt], alo0, alo1, alo2, alo3, bh0, bh1);   // lo*hi
                mma_bf16(acc[nt], ahi0, ahi1, ahi2, ahi3, bl0, bl1);   // hi*lo
            }
        }
        __syncthreads();
    }

    // epilogue: convert to fp16 and store (row = 64 halves = 128 B)
    const int r0 = row0 + wid * 16 + gid;
#pragma unroll
    for (int nt = 0; nt < 8; nt++) {
        const int col = nt * 8 + tig * 2;
        if (r0 < N_NODES)
            *reinterpret_cast<__half2*>(g_support + (size_t)r0 * OUT_DIM + col) =
                __floats2half2_rn(acc[nt][0], acc[nt][1]);
        if (r0 + 8 < N_NODES)
            *reinterpret_cast<__half2*>(g_support + (size_t)(r0 + 8) * OUT_DIM + col) =
                __floats2half2_rn(acc[nt][2], acc[nt][3]);
    }
}

__device__ __forceinline__ void build_body(const float* __restrict__ edge_val,
                                           const int* __restrict__ edge_src,
                                           const int* __restrict__ edge_dst, int blk) {
    int i = blk * 256 + threadIdx.x;
    if (i < N_EDGES) {
        int d = __ldg(&edge_dst[i]);
        int s = __ldg(&edge_src[i]);
        float v = __ldg(&edge_val[i]);
        int pos = atomicAdd(&g_count[d], 1);
        if (pos < CAP)
            g_bucket[(unsigned)d * CAP + (unsigned)pos] = make_int2(s, __float_as_int(v));
    }
}

__global__ __launch_bounds__(256) void fused_kernel(const float* __restrict__ X,
                                                    const float* __restrict__ edge_val,
                                                    const int* __restrict__ edge_src,
                                                    const int* __restrict__ edge_dst) {
    if (blockIdx.x < GEMM_BLOCKS)
        gemm_body(X, blockIdx.x);
    else
        build_body(edge_val, edge_src, edge_dst, blockIdx.x - GEMM_BLOCKS);
}

// ---------------------------------------------------------------------------
// Segmented SpMM over fp16 support: 8 lanes per node (uint4 = 8 halves/lane,
// full 128-B row per group -> single L2 transaction per gather), fp32
// accumulation, bias folded, no atomics, unroll-2.
// ---------------------------------------------------------------------------
__device__ __forceinline__ void fma8_h(float* acc, uint4 s, float v) {
    float2 f0 = __half22float2(*reinterpret_cast<__half2*>(&s.x));
    float2 f1 = __half22float2(*reinterpret_cast<__half2*>(&s.y));
    float2 f2 = __half22float2(*reinterpret_cast<__half2*>(&s.z));
    float2 f3 = __half22float2(*reinterpret_cast<__half2*>(&s.w));
    acc[0] = fmaf(v, f0.x, acc[0]); acc[1] = fmaf(v, f0.y, acc[1]);
    acc[2] = fmaf(v, f1.x, acc[2]); acc[3] = fmaf(v, f1.y, acc[3]);
    acc[4] = fmaf(v, f2.x, acc[4]); acc[5] = fmaf(v, f2.y, acc[5]);
    acc[6] = fmaf(v, f3.x, acc[6]); acc[7] = fmaf(v, f3.y, acc[7]);
}

__global__ __launch_bounds__(256) void spmm_kernel(const float* __restrict__ bias,
                                                   float* __restrict__ out) {
    const int g = (blockIdx.x * 256 + threadIdx.x) >> 3;   // node id (8 lanes/node)
    const int l = threadIdx.x & 7;                         // uint4 lane (8 cols each)
    if (g >= N_NODES) return;

    int cnt = g_count[g];
    if (cnt > CAP) cnt = CAP;
    const int2* bkt = g_bucket + (unsigned)g * CAP;

    float acc[8];
#pragma unroll
    for (int j = 0; j < 8; j++) acc[j] = __ldg(bias + l * 8 + j);

    const uint4* sup = reinterpret_cast<const uint4*>(g_support);  // row = 8 uint4

    int e = 0;
    for (; e + 1 < cnt; e += 2) {
        int2 p0 = bkt[e];
        int2 p1 = bkt[e + 1];
        uint4 s0 = sup[(unsigned)p0.x * 8u + l];
        uint4 s1 = sup[(unsigned)p1.x * 8u + l];
        fma8_h(acc, s0, __int_as_float(p0.y));
        fma8_h(acc, s1, __int_as_float(p1.y));
    }
    if (e < cnt) {
        int2 p = bkt[e];
        uint4 s = sup[(unsigned)p.x * 8u + l];
        fma8_h(acc, s, __int_as_float(p.y));
    }

    float* orow = out + (size_t)g * OUT_DIM + l * 8;
    *reinterpret_cast<float4*>(orow)     = make_float4(acc[0], acc[1], acc[2], acc[3]);
    *reinterpret_cast<float4*>(orow + 4) = make_float4(acc[4], acc[5], acc[6], acc[7]);
}

// ---------------------------------------------------------------------------
extern "C" void kernel_launch(void* const* d_in, const int* in_sizes, int n_in,
                              void* d_out, int out_size) {
    const float* X    = (const float*)d_in[0];     // [50000, 256]
    const float* W    = (const float*)d_in[1];     // [256, 64]
    const float* bias = (const float*)d_in[2];     // [64]
    const float* ev   = (const float*)d_in[3];     // [800000]
    const int*   es   = (const int*)d_in[4];       // [800000] int32
    const int*   ed   = (const int*)d_in[5];       // [800000] int32
    float* out = (float*)d_out;                    // [50000, 64]

    // prep -> fused(gemm+build) -> spmm   (3 nodes, R14 skeleton)
    prep_kernel<<<(N_NODES + 255) / 256, 256>>>(W);
    fused_kernel<<<FUSED_BLOCKS, 256>>>(X, ev, es, ed);
    spmm_kernel<<<(N_NODES * 8 + 255) / 256, 256>>>(bias, out);
}